// round 10
// baseline (speedup 1.0000x reference)
#include <cuda_runtime.h>
#include <cstdint>

#define NE 256
#define NC 48
#define NB 64
#define NT 1024
#define ROWS 128
#define KT   32
#define PADW 36            // 36 % 32 == 4 -> conflict-free strided LDS
#define NTILES 512         // (NB*NT)/ROWS, chunk-major: tile = chunk*64 + chain
#define BUF_FLOATS 6336    // fcw 48*36 + emb 128*36
#define NCRF_BLOCKS 32     // 2 chains per block
#define GRID 148           // = #SMs on sm_100; 1 block/SM forced by smem
#define SMEM_BYTES 118784  // 116KB: 2 per SM impossible (232 > 228) -> exclusive SMs

static __device__ float g_partial[NB];
static __device__ int   g_flags[NTILES];   // zero-init; reset by llh writer
static __device__ int   g_tiles;           // dynamic tile counter
static __device__ int   g_done;

// ---------- packed f32x2 helpers ----------
__device__ __forceinline__ unsigned long long ffma2(unsigned long long a, unsigned long long b,
                                                    unsigned long long c) {
    unsigned long long d;
    asm("fma.rn.f32x2 %0, %1, %2, %3;" : "=l"(d) : "l"(a), "l"(b), "l"(c));
    return d;
}
__device__ __forceinline__ unsigned long long fadd2(unsigned long long a, unsigned long long b) {
    unsigned long long d;
    asm("add.rn.f32x2 %0, %1, %2;" : "=l"(d) : "l"(a), "l"(b));
    return d;
}
__device__ __forceinline__ float2 unpack2(unsigned long long a) {
    float2 f;
    asm("mov.b64 {%0, %1}, %2;" : "=f"(f.x), "=f"(f.y) : "l"(a));
    return f;
}
__device__ __forceinline__ unsigned long long pack2(float x, float y) {
    unsigned long long d;
    asm("mov.b64 %0, {%1, %2};" : "=l"(d) : "f"(x), "f"(y));
    return d;
}
__device__ __forceinline__ float frcp_fast(float x) {
    float r; asm("rcp.approx.f32 %0, %1;" : "=f"(r) : "f"(x)); return r;
}
__device__ __forceinline__ uint32_t smem_u32(const void* p) {
    uint32_t a;
    asm("{ .reg .u64 t; cvta.to.shared.u64 t, %1; cvt.u32.u64 %0, t; }" : "=r"(a) : "l"(p));
    return a;
}
__device__ __forceinline__ void ldgsts16(uint32_t dst, const void* src) {
    asm volatile("cp.async.cg.shared.global [%0], [%1], 16;" :: "r"(dst), "l"(src));
}
__device__ __forceinline__ void barsync(int id, int cnt) {
    asm volatile("bar.sync %0, %1;" :: "r"(id), "r"(cnt) : "memory");
}

// ============================================================================
// Fused kernel: 148 blocks, 512 threads, 116KB smem -> 1 block/SM, all resident.
//  blocks [0,32):    CRF — 2 chains/block, 64 threads each, named-bar sync.
//  blocks [32,148):  GEMM workers — dynamic tile counter, chunk-major tiles,
//                    cp.async double-buffered K pipeline, per-tile flag release.
// ============================================================================
__global__ __launch_bounds__(512, 1) void fused_kernel(
    const int* __restrict__ x, const int* __restrict__ labels,
    const float* __restrict__ emb, const float* __restrict__ fcw,
    const float* __restrict__ fcb, const float* __restrict__ start_trans,
    const float* __restrict__ end_trans, const float* __restrict__ trans,
    float* __restrict__ out, int out_size)
{
    extern __shared__ float sm[];
    __shared__ int t_sh;
    const int tid = threadIdx.x;

    if (blockIdx.x >= NCRF_BLOCKS) {
        // ==================== GEMM worker ====================
        int* x_s = (int*)(sm + 2 * BUF_FLOATS);
        const uint32_t smbase = smem_u32(sm);
        const int tx = tid & 7;    // col group 0..7
        const int ty = tid >> 3;   // row group 0..63

        for (;;) {
            if (tid == 0) t_sh = atomicAdd(&g_tiles, 1);
            __syncthreads();
            const int tile = t_sh;
            __syncthreads();
            if (tile >= NTILES) break;

            const int chain   = tile & 63;
            const int chunk   = tile >> 6;
            const int rowBase = chain * NT + chunk * ROWS;

            if (tid < ROWS) x_s[tid] = x[rowBase + tid];
            __syncthreads();

            #define LOAD_TILE(KIDX, BUF)                                           \
            {                                                                      \
                const int k0 = (KIDX) * KT;                                        \
                const uint32_t fb  = smbase + (BUF) * BUF_FLOATS * 4;              \
                const uint32_t ebs = fb + 1728 * 4;                                \
                if (tid < 384) {                                                   \
                    int r = tid >> 3, k4 = tid & 7;                                \
                    ldgsts16(fb + (r * PADW + 4 * k4) * 4,                         \
                             fcw + r * NE + k0 + 4 * k4);                          \
                }                                                                  \
                for (int i = tid; i < 1024; i += 512) {                            \
                    int r = i >> 3, k4 = i & 7;                                    \
                    ldgsts16(ebs + (r * PADW + 4 * k4) * 4,                        \
                             emb + (size_t)x_s[r] * NE + k0 + 4 * k4);             \
                }                                                                  \
                asm volatile("cp.async.commit_group;");                            \
            }

            LOAD_TILE(0, 0);

            unsigned long long acc[2][6];
            #pragma unroll
            for (int m = 0; m < 2; m++)
                #pragma unroll
                for (int n = 0; n < 6; n++) acc[m][n] = 0ull;

            for (int kt = 0; kt < 8; kt++) {
                if (kt < 7) {
                    LOAD_TILE(kt + 1, (kt + 1) & 1);
                    asm volatile("cp.async.wait_group %0;" :: "n"(1));
                } else {
                    asm volatile("cp.async.wait_group %0;" :: "n"(0));
                }
                __syncthreads();

                const float* fcw_s = sm + (kt & 1) * BUF_FLOATS;
                const float* emb_s = fcw_s + 1728;

                #pragma unroll 4
                for (int k2 = 0; k2 < KT / 2; k2++) {
                    unsigned long long a2[2], w2[6];
                    #pragma unroll
                    for (int m = 0; m < 2; m++)
                        a2[m] = *(const unsigned long long*)&emb_s[(ty + 64 * m) * PADW + 2 * k2];
                    #pragma unroll
                    for (int n = 0; n < 6; n++)
                        w2[n] = *(const unsigned long long*)&fcw_s[(tx + 8 * n) * PADW + 2 * k2];
                    #pragma unroll
                    for (int m = 0; m < 2; m++)
                        #pragma unroll
                        for (int n = 0; n < 6; n++)
                            acc[m][n] = ffma2(a2[m], w2[n], acc[m][n]);
                }
                __syncthreads();
            }
            #undef LOAD_TILE

            #pragma unroll
            for (int m = 0; m < 2; m++) {
                int r = rowBase + ty + 64 * m;
                #pragma unroll
                for (int n = 0; n < 6; n++) {
                    int c = tx + 8 * n;
                    float2 p = unpack2(acc[m][n]);
                    out[(size_t)r * NC + c] = p.x + p.y + __ldg(&fcb[c]);
                }
            }
            __threadfence();
            __syncthreads();
            if (tid == 0) atomicExch(&g_flags[tile], 1);
        }
        return;
    }

    // ==================== CRF: 2 chains per block ====================
    if (tid >= 128) return;

    const int half  = tid >> 6;            // chain within block
    const int ct    = tid & 63;            // chain-local tid
    const int b     = blockIdx.x * 2 + half;
    const int barid = 1 + half;

    float* chsm = sm + half * 192;
    float (*a_sh)[64] = (float(*)[64])chsm;   // [2][64]
    float* red = chsm + 128;                  // [64]

    const float* lg  = out    + (size_t)b * NT * NC;
    const int*   lab = labels + b * NT;

    // acquire-wait: chunk NEED of this chain (flag = NEED*64 + b)
    #define WAIT_CHUNK(NEED)                                                   \
    {                                                                          \
        if (ct == 0) {                                                         \
            volatile int* f = &g_flags[(NEED) * 64 + b];                       \
            while (*f == 0) __nanosleep(64);                                   \
            __threadfence();                                                   \
        }                                                                      \
        barsync(barid, 64);                                                    \
    }

    // ---- branch-free setup: clamped state index ----
    const int cc = (ct < NC) ? ct : (NC - 1);

    unsigned long long Ec2[24];
    #pragma unroll
    for (int j = 0; j < 24; j++) {
        float e0 = __expf(trans[(2 * j)     * NC + cc]) * 0.015625f;  // /64
        float e1 = __expf(trans[(2 * j + 1) * NC + cc]) * 0.015625f;
        Ec2[j] = pack2(e0, e1);
    }

    WAIT_CHUNK(0);
    float a_cur = __expf(start_trans[cc] + lg[cc]);
    a_sh[0][ct] = a_cur;

    float logscale = 0.f;
    float eb[4];
    #pragma unroll
    for (int jj = 0; jj < 4; jj++) eb[jj] = lg[(1 + jj) * NC + cc];
    barsync(barid, 64);

    int p = 0;
    int ready = 0;

    #define CRF_STEP(T, EMIS)                                                  \
    {                                                                          \
        float ex = __expf(EMIS);                                               \
        float r  = a_sh[p][0];                                                 \
        unsigned long long s0 = 0ull, s1 = 0ull, s2 = 0ull, s3 = 0ull;         \
        _Pragma("unroll")                                                      \
        for (int j = 0; j < 12; j += 2) {                                      \
            ulonglong2 u = *(const ulonglong2*)&a_sh[p][4 * j];                \
            ulonglong2 v = *(const ulonglong2*)&a_sh[p][4 * j + 4];            \
            s0 = ffma2(u.x, Ec2[2 * j],     s0);                               \
            s1 = ffma2(u.y, Ec2[2 * j + 1], s1);                               \
            s2 = ffma2(v.x, Ec2[2 * j + 2], s2);                               \
            s3 = ffma2(v.y, Ec2[2 * j + 3], s3);                               \
        }                                                                      \
        float2 sp = unpack2(fadd2(fadd2(s0, s2), fadd2(s1, s3)));              \
        float s = sp.x + sp.y;                                                 \
        bool rn = ((T) & 127) == 0;                                            \
        float sel = rn ? frcp_fast(r) : 1.0f;                                  \
        logscale += rn ? __logf(r) : 0.0f;                                     \
        float anew = s * ex * sel;                                             \
        a_sh[p ^ 1][ct] = anew;                                                \
        a_cur = anew;                                                          \
        barsync(barid, 64);                                                    \
        p ^= 1;                                                                \
    }

    for (int tb = 1; tb + 3 < NT; tb += 4) {
        int need = (tb + 7) >> 7;
        need = (need > 7) ? 7 : need;
        if (need > ready) { WAIT_CHUNK(need); ready = need; }

        float en[4];
        #pragma unroll
        for (int jj = 0; jj < 4; jj++) {
            int tt = tb + 4 + jj;
            tt = (tt < NT) ? tt : (NT - 1);
            en[jj] = lg[tt * NC + cc];
        }
        CRF_STEP(tb + 0, eb[0]);
        CRF_STEP(tb + 1, eb[1]);
        CRF_STEP(tb + 2, eb[2]);
        CRF_STEP(tb + 3, eb[3]);
        eb[0] = en[0]; eb[1] = en[1]; eb[2] = en[2]; eb[3] = en[3];
    }
    CRF_STEP(NT - 3, eb[0]);
    CRF_STEP(NT - 2, eb[1]);
    CRF_STEP(NT - 1, eb[2]);
    #undef CRF_STEP
    #undef WAIT_CHUNK

    // ---- logZ partial ----
    if (ct < NC) red[ct] = a_cur * __expf(end_trans[ct]);
    barsync(barid, 64);
    float logz_part = 0.f;
    if (ct == 0) {
        float s = 0.f;
        #pragma unroll
        for (int i = 0; i < NC; i++) s += red[i];
        logz_part = __logf(s) + logscale + 4254.5374f;   // + 1023*ln(64)
    }
    barsync(barid, 64);

    // ---- numerator (all own chunks ready), fixed-order reduce ----
    float acc = 0.f;
    for (int t = ct; t < NT; t += 64) {
        int lt = lab[t];
        acc += lg[t * NC + lt];
        if (t + 1 < NT) acc += trans[lt * NC + lab[t + 1]];
    }
    if (ct == 0)  acc += start_trans[lab[0]];
    if (ct == 63) acc += end_trans[lab[NT - 1]];
    red[ct] = acc;
    barsync(barid, 64);
    if (ct == 0) {
        float num = 0.f;
        #pragma unroll
        for (int i = 0; i < 64; i++) num += red[i];
        g_partial[b] = num - logz_part;
        __threadfence();
        int v = atomicAdd(&g_done, 1);
        if (v == NB - 1) {                 // last chain: finish + reset state
            float tot = 0.f;
            #pragma unroll
            for (int i = 0; i < NB; i++) tot += g_partial[i];
            out[out_size - 1] = -tot;
            for (int i = 0; i < NTILES; i++) g_flags[i] = 0;
            atomicExch(&g_tiles, 0);
            atomicExch(&g_done, 0);
            __threadfence();
        }
    }
}

extern "C" void kernel_launch(void* const* d_in, const int* in_sizes, int n_in,
                              void* d_out, int out_size)
{
    const int*   x    = (const int*)  d_in[0];
    const int*   lab  = (const int*)  d_in[1];
    const float* emb  = (const float*)d_in[2];
    const float* fcw  = (const float*)d_in[3];
    const float* fcb  = (const float*)d_in[4];
    const float* st   = (const float*)d_in[5];
    const float* et   = (const float*)d_in[6];
    const float* tr   = (const float*)d_in[7];
    float* out = (float*)d_out;

    cudaFuncSetAttribute(fused_kernel, cudaFuncAttributeMaxDynamicSharedMemorySize, SMEM_BYTES);
    fused_kernel<<<GRID, 512, SMEM_BYTES>>>(x, lab, emb, fcw, fcb, st, et, tr, out, out_size);
}

// round 11
// speedup vs baseline: 1.0104x; 1.0104x over previous
#include <cuda_runtime.h>
#include <cstdint>

#define NE 256
#define NC 48
#define NB 64
#define NT 1024
#define ROWS 128
#define KT   32
#define PADW 36            // 36 % 32 == 4 -> conflict-free strided LDS
#define NTILES 512         // chunk-major: tile = chunk*64 + chain
#define BUF_FLOATS 6336    // fcw 48*36 + emb 128*36
#define SUB_FLOATS 12800   // 2 buffers + 128-int x_s per sub-worker
#define NCRF_BLOCKS 32     // 2 chains per block
#define GRID 148           // 1 block/SM forced by smem
#define SMEM_BYTES 118784  // 116KB -> 2/SM impossible -> exclusive SMs

// contiguous sync state, zeroed by cudaMemsetAsync each replay:
// [0..512) tile flags, [512] tile counter, [513] done counter
static __device__ int   g_sync[514];
static __device__ float g_partial[NB];

// ---------- packed f32x2 helpers ----------
__device__ __forceinline__ unsigned long long ffma2(unsigned long long a, unsigned long long b,
                                                    unsigned long long c) {
    unsigned long long d;
    asm("fma.rn.f32x2 %0, %1, %2, %3;" : "=l"(d) : "l"(a), "l"(b), "l"(c));
    return d;
}
__device__ __forceinline__ unsigned long long fadd2(unsigned long long a, unsigned long long b) {
    unsigned long long d;
    asm("add.rn.f32x2 %0, %1, %2;" : "=l"(d) : "l"(a), "l"(b));
    return d;
}
__device__ __forceinline__ float2 unpack2(unsigned long long a) {
    float2 f;
    asm("mov.b64 {%0, %1}, %2;" : "=f"(f.x), "=f"(f.y) : "l"(a));
    return f;
}
__device__ __forceinline__ unsigned long long pack2(float x, float y) {
    unsigned long long d;
    asm("mov.b64 %0, {%1, %2};" : "=l"(d) : "f"(x), "f"(y));
    return d;
}
__device__ __forceinline__ float frcp_fast(float x) {
    float r; asm("rcp.approx.f32 %0, %1;" : "=f"(r) : "f"(x)); return r;
}
__device__ __forceinline__ uint32_t smem_u32(const void* p) {
    uint32_t a;
    asm("{ .reg .u64 t; cvta.to.shared.u64 t, %1; cvt.u32.u64 %0, t; }" : "=r"(a) : "l"(p));
    return a;
}
__device__ __forceinline__ void ldgsts16(uint32_t dst, const void* src) {
    asm volatile("cp.async.cg.shared.global [%0], [%1], 16;" :: "r"(dst), "l"(src));
}
__device__ __forceinline__ void barsync(int id, int cnt) {
    asm volatile("bar.sync %0, %1;" :: "r"(id), "r"(cnt) : "memory");
}

// ============================================================================
// Fused kernel: 148 blocks x 256 threads, 116KB smem -> 1 block/SM.
//  blocks [0,32):    CRF — 2 chains/block, 64 threads each (named bars 1,2).
//  blocks [32,148):  GEMM — 2 independent 128-thread sub-workers (named bars
//                    1,2), each the R9-proven 8x6 cp.async pipeline, pulling
//                    chunk-major tiles from an atomic counter.
// ============================================================================
__global__ __launch_bounds__(256, 1) void fused_kernel(
    const int* __restrict__ x, const int* __restrict__ labels,
    const float* __restrict__ emb, const float* __restrict__ fcw,
    const float* __restrict__ fcb, const float* __restrict__ start_trans,
    const float* __restrict__ end_trans, const float* __restrict__ trans,
    float* __restrict__ out, int out_size)
{
    extern __shared__ float sm[];
    __shared__ int t_sh[2];
    const int tid = threadIdx.x;

    if (blockIdx.x >= NCRF_BLOCKS) {
        // ==================== GEMM: sub-worker w of 2 ====================
        const int w     = tid >> 7;        // 0 or 1
        const int wtid  = tid & 127;
        const int barid = 1 + w;

        float* base_f = sm + w * SUB_FLOATS;
        int*   x_s    = (int*)(base_f + 2 * BUF_FLOATS);
        const uint32_t smbase = smem_u32(base_f);

        const int tx = wtid & 7;    // col group 0..7
        const int ty = wtid >> 3;   // row group 0..15

        for (;;) {
            if (wtid == 0) t_sh[w] = atomicAdd(&g_sync[512], 1);
            barsync(barid, 128);
            const int tile = t_sh[w];
            if (tile >= NTILES) break;

            const int chain   = tile & 63;
            const int chunk   = tile >> 6;
            const int rowBase = chain * NT + chunk * ROWS;

            x_s[wtid] = x[rowBase + wtid];
            barsync(barid, 128);

            #define LOAD_TILE(KIDX, BUF)                                           \
            {                                                                      \
                const int k0 = (KIDX) * KT;                                        \
                const uint32_t fb  = smbase + (BUF) * BUF_FLOATS * 4;              \
                const uint32_t ebs = fb + 1728 * 4;                                \
                for (int i = wtid; i < 384; i += 128) {                            \
                    int r = i >> 3, k4 = i & 7;                                    \
                    ldgsts16(fb + (r * PADW + 4 * k4) * 4,                         \
                             fcw + r * NE + k0 + 4 * k4);                          \
                }                                                                  \
                for (int i = wtid; i < 1024; i += 128) {                           \
                    int r = i >> 3, k4 = i & 7;                                    \
                    ldgsts16(ebs + (r * PADW + 4 * k4) * 4,                        \
                             emb + (size_t)x_s[r] * NE + k0 + 4 * k4);             \
                }                                                                  \
                asm volatile("cp.async.commit_group;");                            \
            }

            LOAD_TILE(0, 0);

            unsigned long long acc[8][6];
            #pragma unroll
            for (int m = 0; m < 8; m++)
                #pragma unroll
                for (int n = 0; n < 6; n++) acc[m][n] = 0ull;

            for (int kt = 0; kt < 8; kt++) {
                if (kt < 7) {
                    LOAD_TILE(kt + 1, (kt + 1) & 1);
                    asm volatile("cp.async.wait_group %0;" :: "n"(1));
                } else {
                    asm volatile("cp.async.wait_group %0;" :: "n"(0));
                }
                barsync(barid, 128);

                const float* fcw_s = base_f + (kt & 1) * BUF_FLOATS;
                const float* emb_s = fcw_s + 1728;

                #pragma unroll 2
                for (int k2 = 0; k2 < KT / 2; k2++) {
                    unsigned long long a2[8], w2[6];
                    #pragma unroll
                    for (int m = 0; m < 8; m++)
                        a2[m] = *(const unsigned long long*)&emb_s[(ty + 16 * m) * PADW + 2 * k2];
                    #pragma unroll
                    for (int n = 0; n < 6; n++)
                        w2[n] = *(const unsigned long long*)&fcw_s[(tx + 8 * n) * PADW + 2 * k2];
                    #pragma unroll
                    for (int m = 0; m < 8; m++)
                        #pragma unroll
                        for (int n = 0; n < 6; n++)
                            acc[m][n] = ffma2(a2[m], w2[n], acc[m][n]);
                }
                barsync(barid, 128);
            }
            #undef LOAD_TILE

            #pragma unroll
            for (int m = 0; m < 8; m++) {
                int r = rowBase + ty + 16 * m;
                #pragma unroll
                for (int n = 0; n < 6; n++) {
                    int c = tx + 8 * n;
                    float2 p = unpack2(acc[m][n]);
                    out[(size_t)r * NC + c] = p.x + p.y + __ldg(&fcb[c]);
                }
            }
            __threadfence();
            barsync(barid, 128);
            if (wtid == 0) atomicExch(&g_sync[tile], 1);
        }
        return;
    }

    // ==================== CRF: 2 chains per block ====================
    if (tid >= 128) return;

    const int half  = tid >> 6;            // chain within block
    const int ct    = tid & 63;            // chain-local tid
    const int b     = blockIdx.x * 2 + half;
    const int barid = 1 + half;

    float* chsm = sm + half * 192;
    float (*a_sh)[64] = (float(*)[64])chsm;   // [2][64]
    float* red = chsm + 128;                  // [64]

    const float* lg  = out    + (size_t)b * NT * NC;
    const int*   lab = labels + b * NT;

    #define WAIT_CHUNK(NEED)                                                   \
    {                                                                          \
        if (ct == 0) {                                                         \
            volatile int* f = &g_sync[(NEED) * 64 + b];                        \
            while (*f == 0) __nanosleep(64);                                   \
            __threadfence();                                                   \
        }                                                                      \
        barsync(barid, 64);                                                    \
    }

    const int cc = (ct < NC) ? ct : (NC - 1);

    unsigned long long Ec2[24];
    #pragma unroll
    for (int j = 0; j < 24; j++) {
        float e0 = __expf(trans[(2 * j)     * NC + cc]) * 0.015625f;  // /64
        float e1 = __expf(trans[(2 * j + 1) * NC + cc]) * 0.015625f;
        Ec2[j] = pack2(e0, e1);
    }

    WAIT_CHUNK(0);
    float a_cur = __expf(start_trans[cc] + lg[cc]);
    a_sh[0][ct] = a_cur;

    float logscale = 0.f;
    float eb[4];
    #pragma unroll
    for (int jj = 0; jj < 4; jj++) eb[jj] = lg[(1 + jj) * NC + cc];
    barsync(barid, 64);

    int p = 0;
    int ready = 0;

    #define CRF_STEP(T, EMIS)                                                  \
    {                                                                          \
        float ex = __expf(EMIS);                                               \
        float r  = a_sh[p][0];                                                 \
        unsigned long long s0 = 0ull, s1 = 0ull, s2 = 0ull, s3 = 0ull;         \
        _Pragma("unroll")                                                      \
        for (int j = 0; j < 12; j += 2) {                                      \
            ulonglong2 u = *(const ulonglong2*)&a_sh[p][4 * j];                \
            ulonglong2 v = *(const ulonglong2*)&a_sh[p][4 * j + 4];            \
            s0 = ffma2(u.x, Ec2[2 * j],     s0);                               \
            s1 = ffma2(u.y, Ec2[2 * j + 1], s1);                               \
            s2 = ffma2(v.x, Ec2[2 * j + 2], s2);                               \
            s3 = ffma2(v.y, Ec2[2 * j + 3], s3);                               \
        }                                                                      \
        float2 sp = unpack2(fadd2(fadd2(s0, s2), fadd2(s1, s3)));              \
        float s = sp.x + sp.y;                                                 \
        bool rn = ((T) & 127) == 0;                                            \
        float sel = rn ? frcp_fast(r) : 1.0f;                                  \
        logscale += rn ? __logf(r) : 0.0f;                                     \
        float anew = s * ex * sel;                                             \
        a_sh[p ^ 1][ct] = anew;                                                \
        a_cur = anew;                                                          \
        barsync(barid, 64);                                                    \
        p ^= 1;                                                                \
    }

    for (int tb = 1; tb + 3 < NT; tb += 4) {
        int need = (tb + 7) >> 7;
        need = (need > 7) ? 7 : need;
        if (need > ready) { WAIT_CHUNK(need); ready = need; }

        float en[4];
        #pragma unroll
        for (int jj = 0; jj < 4; jj++) {
            int tt = tb + 4 + jj;
            tt = (tt < NT) ? tt : (NT - 1);
            en[jj] = lg[tt * NC + cc];
        }
        CRF_STEP(tb + 0, eb[0]);
        CRF_STEP(tb + 1, eb[1]);
        CRF_STEP(tb + 2, eb[2]);
        CRF_STEP(tb + 3, eb[3]);
        eb[0] = en[0]; eb[1] = en[1]; eb[2] = en[2]; eb[3] = en[3];
    }
    CRF_STEP(NT - 3, eb[0]);
    CRF_STEP(NT - 2, eb[1]);
    CRF_STEP(NT - 1, eb[2]);
    #undef CRF_STEP
    #undef WAIT_CHUNK

    // ---- logZ partial ----
    if (ct < NC) red[ct] = a_cur * __expf(end_trans[ct]);
    barsync(barid, 64);
    float logz_part = 0.f;
    if (ct == 0) {
        float s = 0.f;
        #pragma unroll
        for (int i = 0; i < NC; i++) s += red[i];
        logz_part = __logf(s) + logscale + 4254.5374f;   // + 1023*ln(64)
    }
    barsync(barid, 64);

    // ---- numerator (own chunks all ready), fixed-order reduce ----
    float acc = 0.f;
    for (int t = ct; t < NT; t += 64) {
        int lt = lab[t];
        acc += lg[t * NC + lt];
        if (t + 1 < NT) acc += trans[lt * NC + lab[t + 1]];
    }
    if (ct == 0)  acc += start_trans[lab[0]];
    if (ct == 63) acc += end_trans[lab[NT - 1]];
    red[ct] = acc;
    barsync(barid, 64);
    if (ct == 0) {
        float num = 0.f;
        #pragma unroll
        for (int i = 0; i < 64; i++) num += red[i];
        g_partial[b] = num - logz_part;
        __threadfence();
        int v = atomicAdd(&g_sync[513], 1);
        if (v == NB - 1) {                 // last chain writes -llh
            float tot = 0.f;
            #pragma unroll
            for (int i = 0; i < NB; i++) tot += g_partial[i];
            out[out_size - 1] = -tot;
        }
    }
}

extern "C" void kernel_launch(void* const* d_in, const int* in_sizes, int n_in,
                              void* d_out, int out_size)
{
    const int*   x    = (const int*)  d_in[0];
    const int*   lab  = (const int*)  d_in[1];
    const float* emb  = (const float*)d_in[2];
    const float* fcw  = (const float*)d_in[3];
    const float* fcb  = (const float*)d_in[4];
    const float* st   = (const float*)d_in[5];
    const float* et   = (const float*)d_in[6];
    const float* tr   = (const float*)d_in[7];
    float* out = (float*)d_out;

    void* syncAddr = nullptr;
    cudaGetSymbolAddress(&syncAddr, g_sync);
    cudaMemsetAsync(syncAddr, 0, sizeof(int) * 514);

    cudaFuncSetAttribute(fused_kernel, cudaFuncAttributeMaxDynamicSharedMemorySize, SMEM_BYTES);
    fused_kernel<<<GRID, 256, SMEM_BYTES>>>(x, lab, emb, fcw, fcb, st, et, tr, out, out_size);
}